// round 7
// baseline (speedup 1.0000x reference)
#include <cuda_runtime.h>
#include <cuda_bf16.h>
#include <cstdint>

// Problem constants
#define BB 2
#define HH 16
#define SS 2048
#define DD 128
#define NTH 512
#define CTX_ELEMS ((size_t)BB * HH * SS * DD)   // 8388608

// ---- dynamic smem byte offsets (swizzled buffers, 256 B row pitch) ----
#define OFF_QH  0
#define OFF_QL  32768
#define OFF_KVH 65536
#define OFF_KVL 98304
#define OFF_PH  131072
#define OFF_PL  163840
#define OFF_STG 196608            // 2 slots x 16384
#define OFF_RS  229376            // float[128]
#define SMEM_SZ 229888

// ---------------- PTX helpers ----------------
__device__ __forceinline__ uint32_t smem_u32(const void* p) {
    return (uint32_t)__cvta_generic_to_shared(p);
}

// byte offset of bf16 element (r, c) in a swizzled 128x128 tile (row = 256 B)
__device__ __forceinline__ uint32_t swoff(int r, int c) {
    return (uint32_t)(r * 256 + ((((c >> 3) ^ (r & 7)) << 4) | ((c & 7) << 1)));
}

__device__ __forceinline__ void ldsm4(uint32_t (&r)[4], const void* p) {
    uint32_t a = smem_u32(p);
    asm volatile("ldmatrix.sync.aligned.m8n8.x4.shared.b16 {%0,%1,%2,%3}, [%4];"
                 : "=r"(r[0]), "=r"(r[1]), "=r"(r[2]), "=r"(r[3]) : "r"(a));
}

__device__ __forceinline__ void ldsm4t(uint32_t (&r)[4], const void* p) {
    uint32_t a = smem_u32(p);
    asm volatile("ldmatrix.sync.aligned.m8n8.x4.trans.shared.b16 {%0,%1,%2,%3}, [%4];"
                 : "=r"(r[0]), "=r"(r[1]), "=r"(r[2]), "=r"(r[3]) : "r"(a));
}

__device__ __forceinline__ void mma16816(float (&c)[4], const uint32_t (&a)[4],
                                         uint32_t b0, uint32_t b1) {
    asm volatile(
        "mma.sync.aligned.m16n8k16.row.col.f32.bf16.bf16.f32 "
        "{%0,%1,%2,%3},{%4,%5,%6,%7},{%8,%9},{%0,%1,%2,%3};"
        : "+f"(c[0]), "+f"(c[1]), "+f"(c[2]), "+f"(c[3])
        : "r"(a[0]), "r"(a[1]), "r"(a[2]), "r"(a[3]), "r"(b0), "r"(b1));
}

__device__ __forceinline__ uint32_t pack2(__nv_bfloat16 a, __nv_bfloat16 b) {
    __nv_bfloat162 t = __halves2bfloat162(a, b);
    return *reinterpret_cast<uint32_t*>(&t);
}

__device__ __forceinline__ void cpasync16(uint32_t saddr, const void* g) {
    asm volatile("cp.async.cg.shared.global [%0], [%1], 16;"
                 :: "r"(saddr), "l"(g) : "memory");
}

__device__ __forceinline__ void split8(float4 v0, float4 v1, uint4& hi, uint4& lo) {
    float x[8] = {v0.x, v0.y, v0.z, v0.w, v1.x, v1.y, v1.z, v1.w};
    __nv_bfloat16 h[8], l[8];
#pragma unroll
    for (int j = 0; j < 8; j++) {
        h[j] = __float2bfloat16(x[j]);
        l[j] = __float2bfloat16(x[j] - __bfloat162float(h[j]));
    }
    hi = make_uint4(pack2(h[0], h[1]), pack2(h[2], h[3]),
                    pack2(h[4], h[5]), pack2(h[6], h[7]));
    lo = make_uint4(pack2(l[0], l[1]), pack2(l[2], l[3]),
                    pack2(l[4], l[5]), pack2(l[6], l[7]));
}

// stage one 16 KB chunk (32 rows x 128 fp32); each thread stages bytes it
// will itself convert later (self-owned -> no barriers needed around it)
__device__ __forceinline__ void stage_chunk(uint32_t sbase, int slot,
                                            const float* gsrc, int tid) {
    uint32_t sa = sbase + OFF_STG + slot * 16384 + tid * 32;
    const char* g = reinterpret_cast<const char*>(gsrc) + tid * 32;
    cpasync16(sa, g);
    cpasync16(sa + 16, g + 16);
    asm volatile("cp.async.commit_group;" ::: "memory");
}

// barrier-free convert: wait own staged chunk, split rows [ch*32, ch*32+32)
// into KV buffers, then restage the freed slot with next_gsrc.
__device__ __forceinline__ void conv_chunk(unsigned char* smem, uint32_t sbase,
                                           int slot, int ch,
                                           const float* next_gsrc, int tid) {
    asm volatile("cp.async.wait_group 1;" ::: "memory");
    const float* stg = reinterpret_cast<const float*>(smem + OFF_STG + slot * 16384);
    const int rl = tid >> 4;
    const int c  = (tid & 15) * 8;
    const int r  = ch * 32 + rl;
    float4 v0 = *reinterpret_cast<const float4*>(stg + rl * 128 + c);
    float4 v1 = *reinterpret_cast<const float4*>(stg + rl * 128 + c + 4);
    uint4 hi, lo;
    split8(v0, v1, hi, lo);
    const uint32_t off = (uint32_t)(r * 256 + ((((c >> 3) ^ (r & 7))) << 4));
    *reinterpret_cast<uint4*>(smem + OFF_KVH + off) = hi;
    *reinterpret_cast<uint4*>(smem + OFF_KVL + off) = lo;
    stage_chunk(sbase, slot, next_gsrc, tid);
}

// 32x32 warp-tile GEMM over K=128, split hi/lo operands (Ah*Bh + Ah*Bl + Al*Bh)
// product-major MMA order: same-acc reuse distance = 4
template <bool TRANSB>
__device__ __forceinline__ void gemm_tile(const unsigned char* smem,
                                          uint32_t offAH, uint32_t offAL,
                                          uint32_t offBH, uint32_t offBL,
                                          float (&acc)[2][4][4],
                                          int wm, int wn, int lane) {
#pragma unroll 1
    for (int kk = 0; kk < 8; kk++) {
        uint32_t aH[2][4], aL[2][4];
#pragma unroll
        for (int im = 0; im < 2; im++) {
            const int ra = wm * 32 + im * 16 + (lane & 15);
            const int ca = kk * 16 + (lane >> 4) * 8;
            const uint32_t ao = swoff(ra, ca);
            ldsm4(aH[im], smem + offAH + ao);
            ldsm4(aL[im], smem + offAL + ao);
        }
#pragma unroll
        for (int j2 = 0; j2 < 2; j2++) {
            uint32_t bH[4], bL[4];
            uint32_t bo;
            if (!TRANSB) {
                const int rb = wn * 32 + j2 * 16 + (lane >> 4) * 8 + (lane & 7);
                const int cb = kk * 16 + ((lane >> 3) & 1) * 8;
                bo = swoff(rb, cb);
            } else {
                const int rb = kk * 16 + (lane & 7) + ((lane >> 3) & 1) * 8;
                const int cb = wn * 32 + j2 * 16 + (lane >> 4) * 8;
                bo = swoff(rb, cb);
            }
            if (!TRANSB) {
                ldsm4(bH, smem + offBH + bo);
                ldsm4(bL, smem + offBL + bo);
            } else {
                ldsm4t(bH, smem + offBH + bo);
                ldsm4t(bL, smem + offBL + bo);
            }
            // product-major: Ah*Bh (im0, im1), Ah*Bl, Al*Bh
#pragma unroll
            for (int im = 0; im < 2; im++) {
                mma16816(acc[im][2 * j2 + 0], aH[im], bH[0], bH[1]);
                mma16816(acc[im][2 * j2 + 1], aH[im], bH[2], bH[3]);
            }
#pragma unroll
            for (int im = 0; im < 2; im++) {
                mma16816(acc[im][2 * j2 + 0], aH[im], bL[0], bL[1]);
                mma16816(acc[im][2 * j2 + 1], aH[im], bL[2], bL[3]);
            }
#pragma unroll
            for (int im = 0; im < 2; im++) {
                mma16816(acc[im][2 * j2 + 0], aL[im], bH[0], bH[1]);
                mma16816(acc[im][2 * j2 + 1], aL[im], bH[2], bH[3]);
            }
        }
    }
}

// ---------------- main kernel ----------------
__global__ void __launch_bounds__(NTH, 1)
sdpa_kernel(const float* __restrict__ Q, const float* __restrict__ K,
            const float* __restrict__ V, const int* __restrict__ mask,
            const float* __restrict__ scalep, float* __restrict__ out) {
    extern __shared__ unsigned char smem[];
    const uint32_t sbase = smem_u32(smem);
    float* rowsum = reinterpret_cast<float*>(smem + OFF_RS);

    const int tid  = threadIdx.x;
    const int lane = tid & 31;
    const int warp = tid >> 5;
    const int wm = warp >> 2;   // 0..3 -> m offset 32*wm
    const int wn = warp & 3;    // 0..3 -> n offset 32*wn

    const int bh = blockIdx.x >> 4;       // 0..31
    const int qt = blockIdx.x & 15;
    const int b  = bh >> 4;               // H = 16
    const int qbase = qt * 128;

    const float scale = *scalep;
    const float* Qg = Q + ((size_t)bh * SS + qbase) * DD;
    const float* Kg = K + (size_t)bh * SS * DD;
    const float* Vg = V + (size_t)bh * SS * DD;
    const int*   mb = mask + (size_t)b * SS * SS;
    float* ctx = out + ((size_t)bh * SS + qbase) * DD;
    float* att = out + CTX_ELEMS + ((size_t)bh * SS + qbase) * SS;

    // prologue: start staging K(0) chunks 0,1
    stage_chunk(sbase, 0, Kg + 0 * 4096, tid);
    stage_chunk(sbase, 1, Kg + 1 * 4096, tid);

    // load Q (once), split hi/lo into swizzled smem; overlaps the cp.asyncs
    if (tid < 128) rowsum[tid] = 0.f;
#pragma unroll 1
    for (int pass = 0; pass < 4; pass++) {
        const int r = pass * 32 + (tid >> 4);
        const int c = (tid & 15) * 8;
        float4 v0 = *reinterpret_cast<const float4*>(Qg + (size_t)r * DD + c);
        float4 v1 = *reinterpret_cast<const float4*>(Qg + (size_t)r * DD + c + 4);
        uint4 hi, lo;
        split8(v0, v1, hi, lo);
        const uint32_t off = (uint32_t)(r * 256 + ((((c >> 3) ^ (r & 7))) << 4));
        *reinterpret_cast<uint4*>(smem + OFF_QH + off) = hi;
        *reinterpret_cast<uint4*>(smem + OFF_QL + off) = lo;
    }

    float oacc[2][4][4];
#pragma unroll
    for (int im = 0; im < 2; im++)
#pragma unroll
        for (int j = 0; j < 4; j++)
#pragma unroll
            for (int c = 0; c < 4; c++) oacc[im][j][c] = 0.f;

#pragma unroll 1
    for (int kt = 0; kt < SS / 128; kt++) {
        const float* Kt = Kg + (size_t)kt * 128 * DD;
        const float* Vt = Vg + (size_t)kt * 128 * DD;
        const float* Nt = (kt + 1 < SS / 128) ? Kg + (size_t)(kt + 1) * 128 * DD : Kg;

        // bar A: prev PV gemm done reading KV(V) before K converts overwrite
        __syncthreads();

        // convert K chunks 0..3 (barrier-free); restage V chunks 0,1 behind
        conv_chunk(smem, sbase, 0, 0, Kt + 2 * 4096, tid);
        conv_chunk(smem, sbase, 1, 1, Kt + 3 * 4096, tid);
        conv_chunk(smem, sbase, 0, 2, Vt + 0 * 4096, tid);
        conv_chunk(smem, sbase, 1, 3, Vt + 1 * 4096, tid);

        __syncthreads();   // bar B: K tile visible to all

        // ---- S = Q K^T ----
        float sacc[2][4][4];
#pragma unroll
        for (int im = 0; im < 2; im++)
#pragma unroll
            for (int j = 0; j < 4; j++)
#pragma unroll
                for (int c = 0; c < 4; c++) sacc[im][j][c] = 0.f;

        gemm_tile<false>(smem, OFF_QH, OFF_QL, OFF_KVH, OFF_KVL, sacc, wm, wn, lane);

        // ---- epilogue: raw exp -> P hi/lo smem (no mask, no gmem) ----
#pragma unroll
        for (int im = 0; im < 2; im++) {
#pragma unroll
            for (int half = 0; half < 2; half++) {
                const int ql = wm * 32 + im * 16 + (lane >> 2) + half * 8;
#pragma unroll
                for (int jn = 0; jn < 4; jn++) {
                    const int nc = wn * 32 + jn * 8 + (lane & 3) * 2;
                    float e0 = __expf(sacc[im][jn][half * 2 + 0] * scale);
                    float e1 = __expf(sacc[im][jn][half * 2 + 1] * scale);
                    __nv_bfloat16 h0 = __float2bfloat16(e0);
                    __nv_bfloat16 h1 = __float2bfloat16(e1);
                    __nv_bfloat16 l0 = __float2bfloat16(e0 - __bfloat162float(h0));
                    __nv_bfloat16 l1 = __float2bfloat16(e1 - __bfloat162float(h1));
                    const uint32_t po = swoff(ql, nc);
                    *reinterpret_cast<uint32_t*>(smem + OFF_PH + po) = pack2(h0, h1);
                    *reinterpret_cast<uint32_t*>(smem + OFF_PL + po) = pack2(l0, l1);
                }
            }
        }

        __syncthreads();   // bar C: P raw visible; S-gemm KV reads done

        // convert V chunks 0..3 (overwrite KV buffers); restage next-K 0,1
        conv_chunk(smem, sbase, 0, 0, Vt + 2 * 4096, tid);
        conv_chunk(smem, sbase, 1, 1, Vt + 3 * 4096, tid);
        conv_chunk(smem, sbase, 0, 2, Nt + 0 * 4096, tid);
        conv_chunk(smem, sbase, 1, 3, Nt + 1 * 4096, tid);

        // ---- att phase: warp owns rows warp*8..+7 (fully coalesced) ----
        {
            const int r0 = warp * 8;
            const int cc = lane * 4;
#pragma unroll
            for (int i = 0; i < 8; i++) {
                const int r = r0 + i;
                const uint32_t po = swoff(r, cc);
                uint2 hp = *reinterpret_cast<const uint2*>(smem + OFF_PH + po);
                uint2 lp = *reinterpret_cast<const uint2*>(smem + OFF_PL + po);
                __nv_bfloat162 h01 = *reinterpret_cast<__nv_bfloat162*>(&hp.x);
                __nv_bfloat162 h23 = *reinterpret_cast<__nv_bfloat162*>(&hp.y);
                __nv_bfloat162 l01 = *reinterpret_cast<__nv_bfloat162*>(&lp.x);
                __nv_bfloat162 l23 = *reinterpret_cast<__nv_bfloat162*>(&lp.y);
                float e0 = __bfloat162float(__low2bfloat16(h01)) +
                           __bfloat162float(__low2bfloat16(l01));
                float e1 = __bfloat162float(__high2bfloat16(h01)) +
                           __bfloat162float(__high2bfloat16(l01));
                float e2 = __bfloat162float(__low2bfloat16(h23)) +
                           __bfloat162float(__low2bfloat16(l23));
                float e3 = __bfloat162float(__high2bfloat16(h23)) +
                           __bfloat162float(__high2bfloat16(l23));
                int4 mv = *reinterpret_cast<const int4*>(
                    mb + (size_t)(qbase + r) * SS + kt * 128 + cc);
                if (!mv.x) { e0 = 0.f; hp.x &= 0xffff0000u; lp.x &= 0xffff0000u; }
                if (!mv.y) { e1 = 0.f; hp.x &= 0x0000ffffu; lp.x &= 0x0000ffffu; }
                if (!mv.z) { e2 = 0.f; hp.y &= 0xffff0000u; lp.y &= 0xffff0000u; }
                if (!mv.w) { e3 = 0.f; hp.y &= 0x0000ffffu; lp.y &= 0x0000ffffu; }
                *reinterpret_cast<float4*>(att + (size_t)r * SS + kt * 128 + cc) =
                    make_float4(e0, e1, e2, e3);
                *reinterpret_cast<uint2*>(smem + OFF_PH + po) = hp;
                *reinterpret_cast<uint2*>(smem + OFF_PL + po) = lp;
                // rowsum: butterfly over the warp, lane 0 owns the update
                float s = (e0 + e1) + (e2 + e3);
                s += __shfl_xor_sync(0xffffffff, s, 16);
                s += __shfl_xor_sync(0xffffffff, s, 8);
                s += __shfl_xor_sync(0xffffffff, s, 4);
                s += __shfl_xor_sync(0xffffffff, s, 2);
                s += __shfl_xor_sync(0xffffffff, s, 1);
                if (lane == 0) rowsum[r] += s;
            }
        }

        __syncthreads();   // bar D: V + masked P visible

        // ---- O += P V ----
        gemm_tile<true>(smem, OFF_PH, OFF_PL, OFF_KVH, OFF_KVL, oacc, wm, wn, lane);
    }

    asm volatile("cp.async.wait_group 0;" ::: "memory");
    __syncthreads();
    if (tid < 128) rowsum[tid] = 1.f / rowsum[tid];
    __syncthreads();

    // ---- write context = O * rnorm ----
#pragma unroll
    for (int im = 0; im < 2; im++)
#pragma unroll
        for (int half = 0; half < 2; half++) {
            const int ql = wm * 32 + im * 16 + (lane >> 2) + half * 8;
            const float rn = rowsum[ql];
            float* crow = ctx + (size_t)ql * DD;
#pragma unroll
            for (int jn = 0; jn < 4; jn++) {
                const int d0 = wn * 32 + jn * 8 + (lane & 3) * 2;
                *reinterpret_cast<float2*>(crow + d0) =
                    make_float2(oacc[im][jn][half * 2 + 0] * rn,
                                oacc[im][jn][half * 2 + 1] * rn);
            }
        }

    // ---- normalize this CTA's attention slice in place ----
    float2* ap = reinterpret_cast<float2*>(att);
#pragma unroll 4
    for (int i = tid; i < 128 * SS / 2; i += NTH) {
        float rn = rowsum[i >> 10];   // 1024 float2 per row
        float2 v = ap[i];
        v.x *= rn;
        v.y *= rn;
        ap[i] = v;
    }
}

// ---------------- launch ----------------
extern "C" void kernel_launch(void* const* d_in, const int* in_sizes, int n_in,
                              void* d_out, int out_size) {
    const float* Q = (const float*)d_in[0];
    const float* K = (const float*)d_in[1];
    const float* V = (const float*)d_in[2];
    const int*   M = (const int*)d_in[3];
    const float* scale = (const float*)d_in[4];
    float* out = (float*)d_out;

    cudaFuncSetAttribute(sdpa_kernel, cudaFuncAttributeMaxDynamicSharedMemorySize,
                         SMEM_SZ);
    sdpa_kernel<<<512, NTH, SMEM_SZ>>>(Q, K, V, M, scale, out);
}

// round 8
// speedup vs baseline: 1.0015x; 1.0015x over previous
#include <cuda_runtime.h>
#include <cuda_bf16.h>
#include <cstdint>

// Problem constants
#define BB 2
#define HH 16
#define SS 2048
#define DD 128
#define NTH 512
#define CTX_ELEMS ((size_t)BB * HH * SS * DD)   // 8388608

// ---- dynamic smem byte offsets (swizzled buffers, 256 B row pitch) ----
#define OFF_QH  0
#define OFF_QL  32768
#define OFF_KVH 65536
#define OFF_KVL 98304
#define OFF_PH  131072
#define OFF_PL  163840
#define OFF_STG 196608            // 2 slots x 16384
#define OFF_RS  229376            // float[128]
#define SMEM_SZ 229888

// ---------------- PTX helpers ----------------
__device__ __forceinline__ uint32_t smem_u32(const void* p) {
    return (uint32_t)__cvta_generic_to_shared(p);
}

// byte offset of bf16 element (r, c) in a swizzled 128x128 tile (row = 256 B)
__device__ __forceinline__ uint32_t swoff(int r, int c) {
    return (uint32_t)(r * 256 + ((((c >> 3) ^ (r & 7)) << 4) | ((c & 7) << 1)));
}

__device__ __forceinline__ void ldsm4(uint32_t (&r)[4], const void* p) {
    uint32_t a = smem_u32(p);
    asm volatile("ldmatrix.sync.aligned.m8n8.x4.shared.b16 {%0,%1,%2,%3}, [%4];"
                 : "=r"(r[0]), "=r"(r[1]), "=r"(r[2]), "=r"(r[3]) : "r"(a));
}

__device__ __forceinline__ void ldsm4t(uint32_t (&r)[4], const void* p) {
    uint32_t a = smem_u32(p);
    asm volatile("ldmatrix.sync.aligned.m8n8.x4.trans.shared.b16 {%0,%1,%2,%3}, [%4];"
                 : "=r"(r[0]), "=r"(r[1]), "=r"(r[2]), "=r"(r[3]) : "r"(a));
}

__device__ __forceinline__ void mma16816(float (&c)[4], const uint32_t (&a)[4],
                                         uint32_t b0, uint32_t b1) {
    asm volatile(
        "mma.sync.aligned.m16n8k16.row.col.f32.bf16.bf16.f32 "
        "{%0,%1,%2,%3},{%4,%5,%6,%7},{%8,%9},{%0,%1,%2,%3};"
        : "+f"(c[0]), "+f"(c[1]), "+f"(c[2]), "+f"(c[3])
        : "r"(a[0]), "r"(a[1]), "r"(a[2]), "r"(a[3]), "r"(b0), "r"(b1));
}

__device__ __forceinline__ uint32_t pack2(__nv_bfloat16 a, __nv_bfloat16 b) {
    __nv_bfloat162 t = __halves2bfloat162(a, b);
    return *reinterpret_cast<uint32_t*>(&t);
}

__device__ __forceinline__ void cpasync16(uint32_t saddr, const void* g) {
    asm volatile("cp.async.cg.shared.global [%0], [%1], 16;"
                 :: "r"(saddr), "l"(g) : "memory");
}

__device__ __forceinline__ void split8(float4 v0, float4 v1, uint4& hi, uint4& lo) {
    float x[8] = {v0.x, v0.y, v0.z, v0.w, v1.x, v1.y, v1.z, v1.w};
    __nv_bfloat16 h[8], l[8];
#pragma unroll
    for (int j = 0; j < 8; j++) {
        h[j] = __float2bfloat16(x[j]);
        l[j] = __float2bfloat16(x[j] - __bfloat162float(h[j]));
    }
    hi = make_uint4(pack2(h[0], h[1]), pack2(h[2], h[3]),
                    pack2(h[4], h[5]), pack2(h[6], h[7]));
    lo = make_uint4(pack2(l[0], l[1]), pack2(l[2], l[3]),
                    pack2(l[4], l[5]), pack2(l[6], l[7]));
}

// stage one 16 KB chunk (32 rows x 128 fp32); each thread stages bytes it
// will itself convert later (self-owned -> no barriers needed around it)
__device__ __forceinline__ void stage_chunk(uint32_t sbase, int slot,
                                            const float* gsrc, int tid) {
    uint32_t sa = sbase + OFF_STG + slot * 16384 + tid * 32;
    const char* g = reinterpret_cast<const char*>(gsrc) + tid * 32;
    cpasync16(sa, g);
    cpasync16(sa + 16, g + 16);
    asm volatile("cp.async.commit_group;" ::: "memory");
}

// barrier-free convert: wait own staged chunk, split rows [ch*32, ch*32+32)
// into KV buffers, then restage the freed slot with next_gsrc.
__device__ __forceinline__ void conv_chunk(unsigned char* smem, uint32_t sbase,
                                           int slot, int ch,
                                           const float* next_gsrc, int tid) {
    asm volatile("cp.async.wait_group 1;" ::: "memory");
    const float* stg = reinterpret_cast<const float*>(smem + OFF_STG + slot * 16384);
    const int rl = tid >> 4;
    const int c  = (tid & 15) * 8;
    const int r  = ch * 32 + rl;
    float4 v0 = *reinterpret_cast<const float4*>(stg + rl * 128 + c);
    float4 v1 = *reinterpret_cast<const float4*>(stg + rl * 128 + c + 4);
    uint4 hi, lo;
    split8(v0, v1, hi, lo);
    const uint32_t off = (uint32_t)(r * 256 + ((((c >> 3) ^ (r & 7))) << 4));
    *reinterpret_cast<uint4*>(smem + OFF_KVH + off) = hi;
    *reinterpret_cast<uint4*>(smem + OFF_KVL + off) = lo;
    stage_chunk(sbase, slot, next_gsrc, tid);
}

// 32x32 warp-tile GEMM over K=128, split hi/lo operands (Ah*Bh + Ah*Bl + Al*Bh)
// product-major MMA order: same-acc reuse distance = 4
template <bool TRANSB>
__device__ __forceinline__ void gemm_tile(const unsigned char* smem,
                                          uint32_t offAH, uint32_t offAL,
                                          uint32_t offBH, uint32_t offBL,
                                          float (&acc)[2][4][4],
                                          int wm, int wn, int lane) {
#pragma unroll 1
    for (int kk = 0; kk < 8; kk++) {
        uint32_t aH[2][4], aL[2][4];
#pragma unroll
        for (int im = 0; im < 2; im++) {
            const int ra = wm * 32 + im * 16 + (lane & 15);
            const int ca = kk * 16 + (lane >> 4) * 8;
            const uint32_t ao = swoff(ra, ca);
            ldsm4(aH[im], smem + offAH + ao);
            ldsm4(aL[im], smem + offAL + ao);
        }
#pragma unroll
        for (int j2 = 0; j2 < 2; j2++) {
            uint32_t bH[4], bL[4];
            uint32_t bo;
            if (!TRANSB) {
                const int rb = wn * 32 + j2 * 16 + (lane >> 4) * 8 + (lane & 7);
                const int cb = kk * 16 + ((lane >> 3) & 1) * 8;
                bo = swoff(rb, cb);
            } else {
                const int rb = kk * 16 + (lane & 7) + ((lane >> 3) & 1) * 8;
                const int cb = wn * 32 + j2 * 16 + (lane >> 4) * 8;
                bo = swoff(rb, cb);
            }
            if (!TRANSB) {
                ldsm4(bH, smem + offBH + bo);
                ldsm4(bL, smem + offBL + bo);
            } else {
                ldsm4t(bH, smem + offBH + bo);
                ldsm4t(bL, smem + offBL + bo);
            }
            // product-major: Ah*Bh (im0, im1), Ah*Bl, Al*Bh
#pragma unroll
            for (int im = 0; im < 2; im++) {
                mma16816(acc[im][2 * j2 + 0], aH[im], bH[0], bH[1]);
                mma16816(acc[im][2 * j2 + 1], aH[im], bH[2], bH[3]);
            }
#pragma unroll
            for (int im = 0; im < 2; im++) {
                mma16816(acc[im][2 * j2 + 0], aH[im], bL[0], bL[1]);
                mma16816(acc[im][2 * j2 + 1], aH[im], bL[2], bL[3]);
            }
#pragma unroll
            for (int im = 0; im < 2; im++) {
                mma16816(acc[im][2 * j2 + 0], aL[im], bH[0], bH[1]);
                mma16816(acc[im][2 * j2 + 1], aL[im], bH[2], bH[3]);
            }
        }
    }
}

// ---------------- main kernel ----------------
__global__ void __launch_bounds__(NTH, 1)
sdpa_kernel(const float* __restrict__ Q, const float* __restrict__ K,
            const float* __restrict__ V, const int* __restrict__ mask,
            const float* __restrict__ scalep, float* __restrict__ out) {
    extern __shared__ unsigned char smem[];
    const uint32_t sbase = smem_u32(smem);
    float* rowsum = reinterpret_cast<float*>(smem + OFF_RS);

    const int tid  = threadIdx.x;
    const int lane = tid & 31;
    const int warp = tid >> 5;
    const int wm = warp >> 2;   // 0..3 -> m offset 32*wm
    const int wn = warp & 3;    // 0..3 -> n offset 32*wn

    const int bh = blockIdx.x >> 4;       // 0..31
    const int qt = blockIdx.x & 15;
    const int b  = bh >> 4;               // H = 16
    const int qbase = qt * 128;

    const float scale = *scalep;
    const float* Qg = Q + ((size_t)bh * SS + qbase) * DD;
    const float* Kg = K + (size_t)bh * SS * DD;
    const float* Vg = V + (size_t)bh * SS * DD;
    const int*   mb = mask + (size_t)b * SS * SS;
    float* ctx = out + ((size_t)bh * SS + qbase) * DD;
    float* att = out + CTX_ELEMS + ((size_t)bh * SS + qbase) * SS;

    // prologue: start staging K(0) chunks 0,1
    stage_chunk(sbase, 0, Kg + 0 * 4096, tid);
    stage_chunk(sbase, 1, Kg + 1 * 4096, tid);

    // load Q (once), split hi/lo into swizzled smem; overlaps the cp.asyncs
    if (tid < 128) rowsum[tid] = 0.f;
#pragma unroll 1
    for (int pass = 0; pass < 4; pass++) {
        const int r = pass * 32 + (tid >> 4);
        const int c = (tid & 15) * 8;
        float4 v0 = *reinterpret_cast<const float4*>(Qg + (size_t)r * DD + c);
        float4 v1 = *reinterpret_cast<const float4*>(Qg + (size_t)r * DD + c + 4);
        uint4 hi, lo;
        split8(v0, v1, hi, lo);
        const uint32_t off = (uint32_t)(r * 256 + ((((c >> 3) ^ (r & 7))) << 4));
        *reinterpret_cast<uint4*>(smem + OFF_QH + off) = hi;
        *reinterpret_cast<uint4*>(smem + OFF_QL + off) = lo;
    }

    float oacc[2][4][4];
#pragma unroll
    for (int im = 0; im < 2; im++)
#pragma unroll
        for (int j = 0; j < 4; j++)
#pragma unroll
            for (int c = 0; c < 4; c++) oacc[im][j][c] = 0.f;

#pragma unroll 1
    for (int kt = 0; kt < SS / 128; kt++) {
        const float* Kt = Kg + (size_t)kt * 128 * DD;
        const float* Vt = Vg + (size_t)kt * 128 * DD;
        const float* Nt = (kt + 1 < SS / 128) ? Kg + (size_t)(kt + 1) * 128 * DD : Kg;

        // bar A: prev PV gemm done reading KV(V) before K converts overwrite
        __syncthreads();

        // convert K chunks 0..3 (barrier-free); restage V chunks 0,1 behind
        conv_chunk(smem, sbase, 0, 0, Kt + 2 * 4096, tid);
        conv_chunk(smem, sbase, 1, 1, Kt + 3 * 4096, tid);
        conv_chunk(smem, sbase, 0, 2, Vt + 0 * 4096, tid);
        conv_chunk(smem, sbase, 1, 3, Vt + 1 * 4096, tid);

        __syncthreads();   // bar B: K tile visible to all

        // ---- S = Q K^T ----
        float sacc[2][4][4];
#pragma unroll
        for (int im = 0; im < 2; im++)
#pragma unroll
            for (int j = 0; j < 4; j++)
#pragma unroll
                for (int c = 0; c < 4; c++) sacc[im][j][c] = 0.f;

        gemm_tile<false>(smem, OFF_QH, OFF_QL, OFF_KVH, OFF_KVL, sacc, wm, wn, lane);

        // ---- epilogue: raw exp -> P hi/lo smem (no mask, no gmem) ----
#pragma unroll
        for (int im = 0; im < 2; im++) {
#pragma unroll
            for (int half = 0; half < 2; half++) {
                const int ql = wm * 32 + im * 16 + (lane >> 2) + half * 8;
#pragma unroll
                for (int jn = 0; jn < 4; jn++) {
                    const int nc = wn * 32 + jn * 8 + (lane & 3) * 2;
                    float e0 = __expf(sacc[im][jn][half * 2 + 0] * scale);
                    float e1 = __expf(sacc[im][jn][half * 2 + 1] * scale);
                    __nv_bfloat16 h0 = __float2bfloat16(e0);
                    __nv_bfloat16 h1 = __float2bfloat16(e1);
                    __nv_bfloat16 l0 = __float2bfloat16(e0 - __bfloat162float(h0));
                    __nv_bfloat16 l1 = __float2bfloat16(e1 - __bfloat162float(h1));
                    const uint32_t po = swoff(ql, nc);
                    *reinterpret_cast<uint32_t*>(smem + OFF_PH + po) = pack2(h0, h1);
                    *reinterpret_cast<uint32_t*>(smem + OFF_PL + po) = pack2(l0, l1);
                }
            }
        }

        __syncthreads();   // bar C: P raw visible; S-gemm KV reads done

        // convert V chunks 0..3 (overwrite KV buffers); restage next-K 0,1
        conv_chunk(smem, sbase, 0, 0, Vt + 2 * 4096, tid);
        conv_chunk(smem, sbase, 1, 1, Vt + 3 * 4096, tid);
        conv_chunk(smem, sbase, 0, 2, Nt + 0 * 4096, tid);
        conv_chunk(smem, sbase, 1, 3, Nt + 1 * 4096, tid);

        // ---- att phase: warp owns rows warp*8..+7 (fully coalesced) ----
        {
            const int r0 = warp * 8;
            const int cc = lane * 4;
#pragma unroll
            for (int i = 0; i < 8; i++) {
                const int r = r0 + i;
                const uint32_t po = swoff(r, cc);
                uint2 hp = *reinterpret_cast<const uint2*>(smem + OFF_PH + po);
                uint2 lp = *reinterpret_cast<const uint2*>(smem + OFF_PL + po);
                __nv_bfloat162 h01 = *reinterpret_cast<__nv_bfloat162*>(&hp.x);
                __nv_bfloat162 h23 = *reinterpret_cast<__nv_bfloat162*>(&hp.y);
                __nv_bfloat162 l01 = *reinterpret_cast<__nv_bfloat162*>(&lp.x);
                __nv_bfloat162 l23 = *reinterpret_cast<__nv_bfloat162*>(&lp.y);
                float e0 = __bfloat162float(__low2bfloat16(h01)) +
                           __bfloat162float(__low2bfloat16(l01));
                float e1 = __bfloat162float(__high2bfloat16(h01)) +
                           __bfloat162float(__high2bfloat16(l01));
                float e2 = __bfloat162float(__low2bfloat16(h23)) +
                           __bfloat162float(__low2bfloat16(l23));
                float e3 = __bfloat162float(__high2bfloat16(h23)) +
                           __bfloat162float(__high2bfloat16(l23));
                int4 mv = *reinterpret_cast<const int4*>(
                    mb + (size_t)(qbase + r) * SS + kt * 128 + cc);
                if (!mv.x) { e0 = 0.f; hp.x &= 0xffff0000u; lp.x &= 0xffff0000u; }
                if (!mv.y) { e1 = 0.f; hp.x &= 0x0000ffffu; lp.x &= 0x0000ffffu; }
                if (!mv.z) { e2 = 0.f; hp.y &= 0xffff0000u; lp.y &= 0xffff0000u; }
                if (!mv.w) { e3 = 0.f; hp.y &= 0x0000ffffu; lp.y &= 0x0000ffffu; }
                *reinterpret_cast<float4*>(att + (size_t)r * SS + kt * 128 + cc) =
                    make_float4(e0, e1, e2, e3);
                *reinterpret_cast<uint2*>(smem + OFF_PH + po) = hp;
                *reinterpret_cast<uint2*>(smem + OFF_PL + po) = lp;
                // rowsum: butterfly over the warp, lane 0 owns the update
                float s = (e0 + e1) + (e2 + e3);
                s += __shfl_xor_sync(0xffffffff, s, 16);
                s += __shfl_xor_sync(0xffffffff, s, 8);
                s += __shfl_xor_sync(0xffffffff, s, 4);
                s += __shfl_xor_sync(0xffffffff, s, 2);
                s += __shfl_xor_sync(0xffffffff, s, 1);
                if (lane == 0) rowsum[r] += s;
            }
        }

        __syncthreads();   // bar D: V + masked P visible

        // ---- O += P V ----
        gemm_tile<true>(smem, OFF_PH, OFF_PL, OFF_KVH, OFF_KVL, oacc, wm, wn, lane);
    }

    asm volatile("cp.async.wait_group 0;" ::: "memory");
    __syncthreads();
    if (tid < 128) rowsum[tid] = 1.f / rowsum[tid];
    __syncthreads();

    // ---- write context = O * rnorm ----
#pragma unroll
    for (int im = 0; im < 2; im++)
#pragma unroll
        for (int half = 0; half < 2; half++) {
            const int ql = wm * 32 + im * 16 + (lane >> 2) + half * 8;
            const float rn = rowsum[ql];
            float* crow = ctx + (size_t)ql * DD;
#pragma unroll
            for (int jn = 0; jn < 4; jn++) {
                const int d0 = wn * 32 + jn * 8 + (lane & 3) * 2;
                *reinterpret_cast<float2*>(crow + d0) =
                    make_float2(oacc[im][jn][half * 2 + 0] * rn,
                                oacc[im][jn][half * 2 + 1] * rn);
            }
        }

    // ---- normalize this CTA's attention slice in place ----
    float2* ap = reinterpret_cast<float2*>(att);
#pragma unroll 4
    for (int i = tid; i < 128 * SS / 2; i += NTH) {
        float rn = rowsum[i >> 10];   // 1024 float2 per row
        float2 v = ap[i];
        v.x *= rn;
        v.y *= rn;
        ap[i] = v;
    }
}

// ---------------- launch ----------------
extern "C" void kernel_launch(void* const* d_in, const int* in_sizes, int n_in,
                              void* d_out, int out_size) {
    const float* Q = (const float*)d_in[0];
    const float* K = (const float*)d_in[1];
    const float* V = (const float*)d_in[2];
    const int*   M = (const int*)d_in[3];
    const float* scale = (const float*)d_in[4];
    float* out = (float*)d_out;

    cudaFuncSetAttribute(sdpa_kernel, cudaFuncAttributeMaxDynamicSharedMemorySize,
                         SMEM_SZ);
    sdpa_kernel<<<512, NTH, SMEM_SZ>>>(Q, K, V, M, scale, out);
}